// round 16
// baseline (speedup 1.0000x reference)
#include <cuda_runtime.h>
#include <math.h>
#include <stdint.h>

#define NB 2
#define NC 64
#define HW 2304
#define INNER 64
#define HEADS 8
#define DH 8
#define MM 36
#define SCALE 0.35355339059327373f

// ---------------- scratch (device globals; no allocation allowed) ----------------
__device__ float g_qt[NB * HW * INNER];          // q channel-last: [b][p][c]
__device__ float g_kt[NB * HW * INNER];          // k channel-last: [b][p][c]
__device__ float4 g_vlo4[NB * HEADS * HW];       // v channels 0..3:  [b][head][j]
__device__ float4 g_vhi4[NB * HEADS * HW];       // v channels 4..7
__device__ float g_qd[NB * INNER * MM];          // conv+gelu(q): [b][oc][pos36]
__device__ float g_kd[NB * INNER * MM];

// ---------------- kernel A: 1x1 conv qkv + layout transforms ----------------
// grid: 2 b * 72 ptiles(32) * 8 ochunks(24) = 1152 blocks, 256 threads
__global__ void qkv_kernel(const float* __restrict__ f, const float* __restrict__ wqkv) {
    __shared__ float sF[64 * 32];        // [c][pp]
    __shared__ float4 sW4[24 * 16];      // [oidx][c4]
    __shared__ float sOut[32 * 25];      // [pp][oidx], pad 25
    int bid = blockIdx.x;
    int b = bid / 576;
    int rest = bid % 576;
    int p0  = (rest >> 3) * 32;
    int oc0 = (rest & 7) * 24;

    for (int idx = threadIdx.x; idx < 64 * 32; idx += 256) {
        int c = idx >> 5, pp = idx & 31;
        sF[idx] = f[(b * 64 + c) * HW + p0 + pp];
    }
    {
        const float4* wsrc = (const float4*)(wqkv + oc0 * 64);
        for (int idx = threadIdx.x; idx < 384; idx += 256)
            sW4[idx] = wsrc[idx];
    }
    __syncthreads();

    int pp = threadIdx.x & 31;
    int warp = threadIdx.x >> 5;

    float acc0 = 0.f, acc1 = 0.f, acc2 = 0.f;
    const float4* w = sW4 + (warp * 3) * 16;

    #pragma unroll 4
    for (int c4 = 0; c4 < 16; c4++) {
        float v0 = sF[(c4 * 4 + 0) * 32 + pp];
        float v1 = sF[(c4 * 4 + 1) * 32 + pp];
        float v2 = sF[(c4 * 4 + 2) * 32 + pp];
        float v3 = sF[(c4 * 4 + 3) * 32 + pp];
        float4 w0 = w[c4];
        float4 w1 = w[16 + c4];
        float4 w2 = w[32 + c4];
        acc0 = fmaf(w0.x, v0, acc0); acc1 = fmaf(w1.x, v0, acc1); acc2 = fmaf(w2.x, v0, acc2);
        acc0 = fmaf(w0.y, v1, acc0); acc1 = fmaf(w1.y, v1, acc1); acc2 = fmaf(w2.y, v1, acc2);
        acc0 = fmaf(w0.z, v2, acc0); acc1 = fmaf(w1.z, v2, acc1); acc2 = fmaf(w2.z, v2, acc2);
        acc0 = fmaf(w0.w, v3, acc0); acc1 = fmaf(w1.w, v3, acc1); acc2 = fmaf(w2.w, v3, acc2);
    }

    sOut[pp * 25 + warp * 3 + 0] = acc0;
    sOut[pp * 25 + warp * 3 + 1] = acc1;
    sOut[pp * 25 + warp * 3 + 2] = acc2;
    __syncthreads();

    for (int idx = threadIdx.x; idx < 32 * 24; idx += 256) {
        int p_local = idx / 24;
        int oi = idx % 24;
        int o = oc0 + oi;
        int p = p0 + p_local;
        float a = sOut[p_local * 25 + oi];
        if (o < 64) {
            g_qt[(b * HW + p) * 64 + o] = a;
        } else if (o < 128) {
            g_kt[(b * HW + p) * 64 + (o - 64)] = a;
        } else {
            int oi2 = o - 128;
            int hd = oi2 >> 3, c = oi2 & 7;
            float* vout = (float*)(c < 4 ? g_vlo4 : g_vhi4);
            vout[((size_t)(b * HEADS + hd) * HW + p) * 4 + (c & 3)] = a;
        }
    }
}

// ---------------- kernel B: 11x11 stride-8 pad-2 conv + exact GELU ----------------
__global__ void conv_kernel(const float* __restrict__ wq, const float* __restrict__ bq,
                            const float* __restrict__ wk, const float* __restrict__ bk) {
    int bid = blockIdx.x;
    int half = bid & 1;
    int oc = (bid >> 1) & 63;
    int b  = (bid >> 7) & 1;
    int t  = bid >> 8;

    const float* wsrc = (t ? wk : wq) + oc * 64 * 121;
    const float* in   = (t ? g_kt : g_qt) + b * HW * 64;

    __shared__ __align__(16) float sw[121 * 66];
    for (int idx = threadIdx.x; idx < 121 * 64; idx += 288) {
        int ic = idx / 121, tap = idx % 121;
        sw[tap * 66 + ic] = wsrc[idx];
    }
    __syncthreads();

    int warp = threadIdx.x >> 5, lane = threadIdx.x & 31;
    int pos0 = half * 18 + warp * 2;

    int oh0 = pos0 / 6, ow0 = pos0 % 6;
    int oh1 = (pos0 + 1) / 6, ow1 = (pos0 + 1) % 6;
    int ihb0 = oh0 * 8 - 2, iwb0 = ow0 * 8 - 2;
    int ihb1 = oh1 * 8 - 2, iwb1 = ow1 * 8 - 2;

    float2 a0 = {0.f, 0.f}, a1 = {0.f, 0.f};
    #pragma unroll
    for (int kh = 0; kh < 11; kh++) {
        #pragma unroll
        for (int kw = 0; kw < 11; kw++) {
            const float2* wp2 = (const float2*)(sw + (kh * 11 + kw) * 66);
            float2 wv = wp2[lane];
            int ih0 = ihb0 + kh, iw0 = iwb0 + kw;
            if ((unsigned)ih0 < 48u && (unsigned)iw0 < 48u) {
                const float2* ip = (const float2*)(in + (ih0 * 48 + iw0) * 64);
                float2 iv = ip[lane];
                a0.x = fmaf(iv.x, wv.x, a0.x);
                a0.y = fmaf(iv.y, wv.y, a0.y);
            }
            int ih1 = ihb1 + kh, iw1 = iwb1 + kw;
            if ((unsigned)ih1 < 48u && (unsigned)iw1 < 48u) {
                const float2* ip = (const float2*)(in + (ih1 * 48 + iw1) * 64);
                float2 iv = ip[lane];
                a1.x = fmaf(iv.x, wv.x, a1.x);
                a1.y = fmaf(iv.y, wv.y, a1.y);
            }
        }
    }
    float acc0 = a0.x + a0.y;
    float acc1 = a1.x + a1.y;
    #pragma unroll
    for (int off = 16; off; off >>= 1) {
        acc0 += __shfl_xor_sync(0xffffffffu, acc0, off);
        acc1 += __shfl_xor_sync(0xffffffffu, acc1, off);
    }
    if (lane == 0) {
        float bias = (t ? bk : bq)[oc];
        float* dst = (t ? g_kd : g_qd) + (b * 64 + oc) * MM;
        float x0 = acc0 + bias;
        dst[pos0] = 0.5f * x0 * (1.0f + erff(x0 * 0.7071067811865476f));
        float x1 = acc1 + bias;
        dst[pos0 + 1] = 0.5f * x1 * (1.0f + erff(x1 * 0.7071067811865476f));
    }
}

// ---------------- kernel D: fused dots + pos-logits + softmax + attn@v ----------------
// Block = 128 threads = 4 warps, handles 16 rows of one (b,hd).
// warp: rg = warp>>1 (rows rg*8..rg*8+7), half = warp&1 (0: v ch0-3, 1: v ch4-7).
// grid: 36864/16 = 2304 blocks.

#define FMA2(d, a, b, c) asm("fma.rn.f32x2 %0, %1, %2, %3;" : "=l"(d) : "l"(a), "l"(b), "l"(c))
#define PACK2(out, x)    asm("mov.b64 %0, {%1, %1};" : "=l"(out) : "r"(x))
#define UNPK2(lo, hi, in) asm("mov.b64 {%0, %1}, %2;" : "=r"(lo), "=r"(hi) : "l"(in))

// block smem floats:
//  0    sQ[128]     (dead after sA/sB; smB[48] aliased here)
//  128  sD[40]
//  168  sA[16*48]
//  936  sB[16*48]
//  1704 eC2[144*16] ([s][row]; byte offset 6816 % 16 == 0)
//  4008 rsum[16]
#define WSHB 4024

__global__ void __launch_bounds__(128, 6)
attn_kernel(const float* __restrict__ pos_h, const float* __restrict__ pos_w,
            float* __restrict__ out) {
    __shared__ float sh[WSHB];
    int tid = threadIdx.x;
    int warp = tid >> 5, lane = tid & 31;
    int rg = warp >> 1, half = warp & 1;
    int g0 = rg * 8;

    int w = blockIdx.x;                 // < 2304
    int bh = w / 144;                   // 2304/16 = 144 row-groups per (b,h)
    int i0 = (w % 144) * 16;
    int b = bh >> 3, hd = bh & 7;

    float* sQ   = sh;             // 128
    float* sD   = sh + 128;       // 40
    float* sA   = sh + 168;       // 16*48
    float* sB   = sh + 936;       // 16*48
    float* eC2  = sh + 1704;      // 144*16, [s][row]
    float* rsum = sh + 4008;      // 16
    float* smB  = sh;             // alias sQ: sumB16[row*3+phi], 48

    // stage q for 16 rows: sQ[row*8+c]
    sQ[tid] = g_qt[((size_t)(b * HW + i0 + (tid >> 3))) * 64 + hd * 8 + (tid & 7)];
    // inline dots: sD[t] = SCALE * sum_c qd[c][i36] * kd[c][t]
    if (tid < 36) {
        int i36 = i0 >> 6;
        const float* qd = g_qd + (b * 64 + hd * 8) * MM;
        const float* kd = g_kd + (b * 64 + hd * 8) * MM;
        float s = 0.f;
        #pragma unroll
        for (int c = 0; c < 8; c++)
            s = fmaf(__ldg(&qd[c * MM + i36]), __ldg(&kd[c * MM + tid]), s);
        sD[tid] = s * SCALE;
    }
    __syncthreads();

    // raw A/B for 16 rows (block-cooperative)
    for (int idx = tid; idx < 16 * 48; idx += 128) {
        int r = idx / 48, jh = idx % 48;
        float a = 0.f, bb = 0.f;
        #pragma unroll
        for (int c = 0; c < 8; c++) {
            float qv = sQ[r * 8 + c];
            a  = fmaf(qv, __ldg(&pos_h[c * 48 + jh]), a);
            bb = fmaf(qv, __ldg(&pos_w[c * 48 + jh]), bb);
        }
        sA[idx] = a;
        sB[idx] = bb;
    }
    __syncthreads();

    // per-warp maxes over its own row group (lo/hi warp pairs compute identical values)
    float mA[8], mB[8], mD = -1e30f;
    #pragma unroll
    for (int r = 0; r < 8; r++) { mA[r] = -1e30f; mB[r] = -1e30f; }
    for (int t = lane; t < 48; t += 32) {
        #pragma unroll
        for (int r = 0; r < 8; r++) {
            mA[r] = fmaxf(mA[r], sA[(g0 + r) * 48 + t]);
            mB[r] = fmaxf(mB[r], sB[(g0 + r) * 48 + t]);
        }
    }
    for (int t = lane; t < 36; t += 32) mD = fmaxf(mD, sD[t]);
    #pragma unroll
    for (int off = 16; off; off >>= 1) {
        mD = fmaxf(mD, __shfl_xor_sync(0xffffffffu, mD, off));
        #pragma unroll
        for (int r = 0; r < 8; r++) {
            mA[r] = fmaxf(mA[r], __shfl_xor_sync(0xffffffffu, mA[r], off));
            mB[r] = fmaxf(mB[r], __shfl_xor_sync(0xffffffffu, mB[r], off));
        }
    }
    __syncthreads();   // all max-reads complete before exp overwrites

    // exp in place — WRITE-ONCE partition (fixes r15 double-exp race):
    //   sA rows: half==0 warps only (warp0 -> rows 0-7, warp2 -> rows 8-15)
    //   sB rows: half==1 warps only (warp1 -> rows 0-7, warp3 -> rows 8-15)
    //   sD:      warp 0 only
    if (half == 0) {
        for (int t = lane; t < 48; t += 32) {
            #pragma unroll
            for (int r = 0; r < 8; r++)
                sA[(g0 + r) * 48 + t] = __expf(sA[(g0 + r) * 48 + t] - mA[r]);
        }
    } else {
        for (int t = lane; t < 48; t += 32) {
            #pragma unroll
            for (int r = 0; r < 8; r++)
                sB[(g0 + r) * 48 + t] = __expf(sB[(g0 + r) * 48 + t] - mB[r]);
        }
    }
    if (warp == 0)
        for (int t = lane; t < 36; t += 32) sD[t] = __expf(sD[t] - mD);
    __syncthreads();

    // eC2[s][row] = eA[row][s/3] * eD[s>>2]   (sQ dead; smB written below)
    for (int idx = tid; idx < 144 * 4; idx += 128) {
        int s = idx >> 2, quad = idx & 3;
        float d = sD[s >> 2];
        int jh = s / 3;
        int g = quad * 4;
        float4 v;
        v.x = sA[(g + 0) * 48 + jh] * d;
        v.y = sA[(g + 1) * 48 + jh] * d;
        v.z = sA[(g + 2) * 48 + jh] * d;
        v.w = sA[(g + 3) * 48 + jh] * d;
        *(float4*)&eC2[s * 16 + g] = v;
    }
    // sumB16[row][phi]
    if (tid < 48) {
        int r = tid / 3, phi = tid % 3;
        float s16 = 0.f;
        #pragma unroll
        for (int u = 0; u < 16; u++) s16 += sB[r * 48 + phi * 16 + u];
        smB[r * 3 + phi] = s16;
    }
    __syncthreads();

    // rsum[row] = sum_s eC2[s][row] * smB[row*3 + s%3]
    {
        int r = tid >> 3, part = tid & 7;
        float acc = 0.f;
        for (int s = part; s < 144; s += 8)
            acc = fmaf(eC2[s * 16 + r], smB[r * 3 + s % 3], acc);
        acc += __shfl_xor_sync(0xffffffffu, acc, 4);
        acc += __shfl_xor_sync(0xffffffffu, acc, 2);
        acc += __shfl_xor_sync(0xffffffffu, acc, 1);
        if (part == 0) rsum[r] = acc;
    }

    // register b-values for this warp's rows: jw = (lane+32t)%48, period 3
    int w0 = lane;
    int w1 = (lane < 16) ? lane + 32 : lane - 16;
    int w2 = lane + 16;
    float bva[8], bvb[8], bvc[8];
    #pragma unroll
    for (int r = 0; r < 8; r++) {
        bva[r] = sB[(g0 + r) * 48 + w0];
        bvb[r] = sB[(g0 + r) * 48 + w1];
        bvc[r] = sB[(g0 + r) * 48 + w2];
    }
    __syncthreads();   // rsum visible before epilogue

    const ulonglong2* vsl = (const ulonglong2*)(half ? g_vhi4 : g_vlo4)
                            + (size_t)(b * HEADS + hd) * HW;

    unsigned long long acc[8][2];
    #pragma unroll
    for (int r = 0; r < 8; r++) { acc[r][0] = 0ull; acc[r][1] = 0ull; }

    int j = lane;
    int s = lane >> 4;

#define STEP(JOFS, SOFS, BV) { \
        ulonglong2 L = vsl[j + (JOFS)]; \
        float4 c0 = *(const float4*)&eC2[(s + (SOFS)) * 16 + g0]; \
        float4 c1 = *(const float4*)&eC2[(s + (SOFS)) * 16 + g0 + 4]; \
        unsigned long long q0, q1, q2, q3, q4, q5, q6, q7; \
        PACK2(q0, __float_as_uint(c0.x * BV[0])); \
        PACK2(q1, __float_as_uint(c0.y * BV[1])); \
        PACK2(q2, __float_as_uint(c0.z * BV[2])); \
        PACK2(q3, __float_as_uint(c0.w * BV[3])); \
        PACK2(q4, __float_as_uint(c1.x * BV[4])); \
        PACK2(q5, __float_as_uint(c1.y * BV[5])); \
        PACK2(q6, __float_as_uint(c1.z * BV[6])); \
        PACK2(q7, __float_as_uint(c1.w * BV[7])); \
        FMA2(acc[0][0], q0, L.x, acc[0][0]); FMA2(acc[0][1], q0, L.y, acc[0][1]); \
        FMA2(acc[1][0], q1, L.x, acc[1][0]); FMA2(acc[1][1], q1, L.y, acc[1][1]); \
        FMA2(acc[2][0], q2, L.x, acc[2][0]); FMA2(acc[2][1], q2, L.y, acc[2][1]); \
        FMA2(acc[3][0], q3, L.x, acc[3][0]); FMA2(acc[3][1], q3, L.y, acc[3][1]); \
        FMA2(acc[4][0], q4, L.x, acc[4][0]); FMA2(acc[4][1], q4, L.y, acc[4][1]); \
        FMA2(acc[5][0], q5, L.x, acc[5][0]); FMA2(acc[5][1], q5, L.y, acc[5][1]); \
        FMA2(acc[6][0], q6, L.x, acc[6][0]); FMA2(acc[6][1], q6, L.y, acc[6][1]); \
        FMA2(acc[7][0], q7, L.x, acc[7][0]); FMA2(acc[7][1], q7, L.y, acc[7][1]); \
    }

    #pragma unroll 1
    for (int tt = 0; tt < 24; tt++) {
        STEP(0,  0, bva)
        STEP(32, 2, bvb)
        STEP(64, 4, bvc)
        j += 96;
        s += 6;
    }
#undef STEP

    // reduce + write: this warp covers 8 rows x 4 channels (half-selected)
    #pragma unroll
    for (int r = 0; r < 8; r++) {
        float f0, f1, f2, f3;
        unsigned u0, u1;
        UNPK2(u0, u1, acc[r][0]); f0 = __uint_as_float(u0); f1 = __uint_as_float(u1);
        UNPK2(u0, u1, acc[r][1]); f2 = __uint_as_float(u0); f3 = __uint_as_float(u1);
        #pragma unroll
        for (int off = 16; off; off >>= 1) {
            f0 += __shfl_xor_sync(0xffffffffu, f0, off);
            f1 += __shfl_xor_sync(0xffffffffu, f1, off);
            f2 += __shfl_xor_sync(0xffffffffu, f2, off);
            f3 += __shfl_xor_sync(0xffffffffu, f3, off);
        }
        float rr = f0;
        if (lane == 1) rr = f1;
        if (lane == 2) rr = f2;
        if (lane == 3) rr = f3;
        if (lane < 4)
            out[((size_t)(b * 64) + hd * 8 + half * 4 + lane) * HW + i0 + g0 + r]
                = rr / rsum[g0 + r];
    }
}

// ---------------- launch ----------------
extern "C" void kernel_launch(void* const* d_in, const int* in_sizes, int n_in,
                              void* d_out, int out_size) {
    const float* f    = (const float*)d_in[0];
    const float* wqkv = (const float*)d_in[1];
    const float* wq   = (const float*)d_in[2];
    const float* bq   = (const float*)d_in[3];
    const float* wk   = (const float*)d_in[4];
    const float* bk   = (const float*)d_in[5];
    const float* ph   = (const float*)d_in[6];
    const float* pw   = (const float*)d_in[7];
    float* out = (float*)d_out;

    qkv_kernel<<<1152, 256>>>(f, wqkv);
    conv_kernel<<<512, 288>>>(wq, bq, wk, bk);
    attn_kernel<<<2304, 128>>>(ph, pw, out);
}

// round 17
// speedup vs baseline: 1.3400x; 1.3400x over previous
#include <cuda_runtime.h>
#include <math.h>
#include <stdint.h>

#define NB 2
#define NC 64
#define HW 2304
#define INNER 64
#define HEADS 8
#define DH 8
#define MM 36
#define SCALE 0.35355339059327373f

// ---------------- scratch (device globals; no allocation allowed) ----------------
__device__ float g_qt[NB * HW * INNER];          // q channel-last: [b][p][c]
__device__ float g_kt[NB * HW * INNER];          // k channel-last: [b][p][c]
__device__ float4 g_vlo4[NB * HEADS * HW];       // v channels 0..3:  [b][head][j]
__device__ float4 g_vhi4[NB * HEADS * HW];       // v channels 4..7
__device__ float g_qd[NB * INNER * MM];          // conv+gelu(q): [b][oc][pos36]
__device__ float g_kd[NB * INNER * MM];

// ---------------- kernel A: 1x1 conv qkv + layout transforms ----------------
// grid: 2 b * 72 ptiles(32) * 8 ochunks(24) = 1152 blocks, 256 threads
// LDS-only inner loop; coalesced epilogue via smem staging
__global__ void qkv_kernel(const float* __restrict__ f, const float* __restrict__ wqkv) {
    __shared__ float sF[64 * 32];        // [c][pp]
    __shared__ float4 sW4[24 * 16];      // [oidx][c4]
    __shared__ float sOut[32 * 25];      // [pp][oidx], pad 25
    int bid = blockIdx.x;
    int b = bid / 576;
    int rest = bid % 576;
    int p0  = (rest >> 3) * 32;
    int oc0 = (rest & 7) * 24;

    for (int idx = threadIdx.x; idx < 64 * 32; idx += 256) {
        int c = idx >> 5, pp = idx & 31;
        sF[idx] = f[(b * 64 + c) * HW + p0 + pp];
    }
    {
        const float4* wsrc = (const float4*)(wqkv + oc0 * 64);   // linear 384 float4
        for (int idx = threadIdx.x; idx < 384; idx += 256)
            sW4[idx] = wsrc[idx];
    }
    __syncthreads();

    int pp = threadIdx.x & 31;
    int warp = threadIdx.x >> 5;   // 0..7, each warp owns 3 outputs

    float acc0 = 0.f, acc1 = 0.f, acc2 = 0.f;
    const float4* w = sW4 + (warp * 3) * 16;

    #pragma unroll 4
    for (int c4 = 0; c4 < 16; c4++) {
        float v0 = sF[(c4 * 4 + 0) * 32 + pp];
        float v1 = sF[(c4 * 4 + 1) * 32 + pp];
        float v2 = sF[(c4 * 4 + 2) * 32 + pp];
        float v3 = sF[(c4 * 4 + 3) * 32 + pp];
        float4 w0 = w[c4];
        float4 w1 = w[16 + c4];
        float4 w2 = w[32 + c4];
        acc0 = fmaf(w0.x, v0, acc0); acc1 = fmaf(w1.x, v0, acc1); acc2 = fmaf(w2.x, v0, acc2);
        acc0 = fmaf(w0.y, v1, acc0); acc1 = fmaf(w1.y, v1, acc1); acc2 = fmaf(w2.y, v1, acc2);
        acc0 = fmaf(w0.z, v2, acc0); acc1 = fmaf(w1.z, v2, acc1); acc2 = fmaf(w2.z, v2, acc2);
        acc0 = fmaf(w0.w, v3, acc0); acc1 = fmaf(w1.w, v3, acc1); acc2 = fmaf(w2.w, v3, acc2);
    }

    // stage results: sOut[pp][warp*3 + k]   (stride 25 odd -> conflict-free)
    sOut[pp * 25 + warp * 3 + 0] = acc0;
    sOut[pp * 25 + warp * 3 + 1] = acc1;
    sOut[pp * 25 + warp * 3 + 2] = acc2;
    __syncthreads();

    // coalesced store: idx -> (p_local, oi), consecutive lanes = consecutive oi
    for (int idx = threadIdx.x; idx < 32 * 24; idx += 256) {
        int p_local = idx / 24;
        int oi = idx % 24;
        int o = oc0 + oi;
        int p = p0 + p_local;
        float a = sOut[p_local * 25 + oi];
        if (o < 64) {
            g_qt[(b * HW + p) * 64 + o] = a;
        } else if (o < 128) {
            g_kt[(b * HW + p) * 64 + (o - 64)] = a;
        } else {
            int oi2 = o - 128;
            int hd = oi2 >> 3, c = oi2 & 7;
            float* vout = (float*)(c < 4 ? g_vlo4 : g_vhi4);
            vout[((size_t)(b * HEADS + hd) * HW + p) * 4 + (c & 3)] = a;
        }
    }
}

// ---------------- kernel B: 11x11 stride-8 pad-2 conv + exact GELU ----------------
__global__ void conv_kernel(const float* __restrict__ wq, const float* __restrict__ bq,
                            const float* __restrict__ wk, const float* __restrict__ bk) {
    int bid = blockIdx.x;
    int half = bid & 1;
    int oc = (bid >> 1) & 63;
    int b  = (bid >> 7) & 1;
    int t  = bid >> 8;

    const float* wsrc = (t ? wk : wq) + oc * 64 * 121;   // layout [ic][tap], linear
    const float* in   = (t ? g_kt : g_qt) + b * HW * 64;

    __shared__ __align__(16) float sw[121 * 66];
    for (int idx = threadIdx.x; idx < 121 * 64; idx += 288) {
        int ic = idx / 121, tap = idx % 121;
        sw[tap * 66 + ic] = wsrc[idx];
    }
    __syncthreads();

    int warp = threadIdx.x >> 5, lane = threadIdx.x & 31;
    int pos0 = half * 18 + warp * 2;

    int oh0 = pos0 / 6, ow0 = pos0 % 6;
    int oh1 = (pos0 + 1) / 6, ow1 = (pos0 + 1) % 6;
    int ihb0 = oh0 * 8 - 2, iwb0 = ow0 * 8 - 2;
    int ihb1 = oh1 * 8 - 2, iwb1 = ow1 * 8 - 2;

    float2 a0 = {0.f, 0.f}, a1 = {0.f, 0.f};
    #pragma unroll
    for (int kh = 0; kh < 11; kh++) {
        #pragma unroll
        for (int kw = 0; kw < 11; kw++) {
            const float2* wp2 = (const float2*)(sw + (kh * 11 + kw) * 66);
            float2 wv = wp2[lane];
            int ih0 = ihb0 + kh, iw0 = iwb0 + kw;
            if ((unsigned)ih0 < 48u && (unsigned)iw0 < 48u) {
                const float2* ip = (const float2*)(in + (ih0 * 48 + iw0) * 64);
                float2 iv = ip[lane];
                a0.x = fmaf(iv.x, wv.x, a0.x);
                a0.y = fmaf(iv.y, wv.y, a0.y);
            }
            int ih1 = ihb1 + kh, iw1 = iwb1 + kw;
            if ((unsigned)ih1 < 48u && (unsigned)iw1 < 48u) {
                const float2* ip = (const float2*)(in + (ih1 * 48 + iw1) * 64);
                float2 iv = ip[lane];
                a1.x = fmaf(iv.x, wv.x, a1.x);
                a1.y = fmaf(iv.y, wv.y, a1.y);
            }
        }
    }
    float acc0 = a0.x + a0.y;
    float acc1 = a1.x + a1.y;
    #pragma unroll
    for (int off = 16; off; off >>= 1) {
        acc0 += __shfl_xor_sync(0xffffffffu, acc0, off);
        acc1 += __shfl_xor_sync(0xffffffffu, acc1, off);
    }
    if (lane == 0) {
        float bias = (t ? bk : bq)[oc];
        float* dst = (t ? g_kd : g_qd) + (b * 64 + oc) * MM;
        float x0 = acc0 + bias;
        dst[pos0] = 0.5f * x0 * (1.0f + erff(x0 * 0.7071067811865476f));
        float x1 = acc1 + bias;
        dst[pos0 + 1] = 0.5f * x1 * (1.0f + erff(x1 * 0.7071067811865476f));
    }
}

// ---------------- kernel D: fused dots + pos-logits + softmax + attn@v ----------------
// one warp per 8 consecutive output rows; grid 1152 blocks, 128 threads

#define FMA2(d, a, b, c) asm("fma.rn.f32x2 %0, %1, %2, %3;" : "=l"(d) : "l"(a), "l"(b), "l"(c))
#define PACK2(out, x)    asm("mov.b64 %0, {%1, %1};" : "=l"(out) : "r"(x))
#define UNPK2(lo, hi, in) asm("mov.b64 {%0, %1}, %2;" : "=r"(lo), "=r"(hi) : "l"(in))

// per-warp smem floats:
//  0    sQ[64]      (dead after sA/sB built; smB[24] aliased here)
//  64   sD[40]
//  104  sA[8*48]
//  488  sB[8*48]
//  872  eC2[144*8]  (layout [s][r], 16B-aligned)
//  2024 rsum[8]
#define WSH 2032

__global__ void __launch_bounds__(128, 4)
attn_kernel(const float* __restrict__ pos_h, const float* __restrict__ pos_w,
            float* __restrict__ out) {
    __shared__ float sh[4][WSH];
    int warp = threadIdx.x >> 5, lane = threadIdx.x & 31;
    int w = blockIdx.x * 4 + warp;              // global warp id < 4608
    int bh = w / 288;                           // 2304/8 = 288 row-groups per (b,h)
    int i0 = (w % 288) * 8;
    int b = bh >> 3, hd = bh & 7;

    float* sQ   = sh[warp];          // 64
    float* sD   = sh[warp] + 64;     // 40
    float* sA   = sh[warp] + 104;    // 8*48
    float* sB   = sh[warp] + 488;    // 8*48
    float* eC2  = sh[warp] + 872;    // 144*8, [s][r]
    float* rsum = sh[warp] + 2024;   // 8
    float* smB  = sh[warp];          // alias sQ: sumB16[r*3+phi], 24

    // stage q for 8 rows: sQ[r*8+c]
    {
        int t = lane;
        sQ[t] = g_qt[((size_t)(b * HW + i0 + (t >> 3))) * 64 + hd * 8 + (t & 7)];
        t += 32;
        sQ[t] = g_qt[((size_t)(b * HW + i0 + (t >> 3))) * 64 + hd * 8 + (t & 7)];
    }
    // inline dots: sD[t] = SCALE * sum_c qd[c][i36] * kd[c][t]   (i36 = i0>>6)
    {
        int i36 = i0 >> 6;
        const float* qd = g_qd + (b * 64 + hd * 8) * MM;
        const float* kd = g_kd + (b * 64 + hd * 8) * MM;
        for (int t = lane; t < 36; t += 32) {
            float s = 0.f;
            #pragma unroll
            for (int c = 0; c < 8; c++)
                s = fmaf(__ldg(&qd[c * MM + i36]), __ldg(&kd[c * MM + t]), s);
            sD[t] = s * SCALE;
        }
    }
    __syncwarp();

    // raw A/B for 8 rows
    for (int jh = lane; jh < 48; jh += 32) {
        float phv[8], pwv[8];
        #pragma unroll
        for (int c = 0; c < 8; c++) {
            phv[c] = __ldg(&pos_h[c * 48 + jh]);
            pwv[c] = __ldg(&pos_w[c * 48 + jh]);
        }
        #pragma unroll
        for (int r = 0; r < 8; r++) {
            float a = 0.f, bb = 0.f;
            #pragma unroll
            for (int c = 0; c < 8; c++) {
                float qv = sQ[r * 8 + c];
                a  = fmaf(qv, phv[c], a);
                bb = fmaf(qv, pwv[c], bb);
            }
            sA[r * 48 + jh] = a;
            sB[r * 48 + jh] = bb;
        }
    }
    __syncwarp();

    // per-component maxes
    float mA[8], mB[8], mD = -1e30f;
    #pragma unroll
    for (int r = 0; r < 8; r++) { mA[r] = -1e30f; mB[r] = -1e30f; }
    for (int t = lane; t < 48; t += 32) {
        #pragma unroll
        for (int r = 0; r < 8; r++) {
            mA[r] = fmaxf(mA[r], sA[r * 48 + t]);
            mB[r] = fmaxf(mB[r], sB[r * 48 + t]);
        }
    }
    for (int t = lane; t < 36; t += 32) mD = fmaxf(mD, sD[t]);
    #pragma unroll
    for (int off = 16; off; off >>= 1) {
        mD = fmaxf(mD, __shfl_xor_sync(0xffffffffu, mD, off));
        #pragma unroll
        for (int r = 0; r < 8; r++) {
            mA[r] = fmaxf(mA[r], __shfl_xor_sync(0xffffffffu, mA[r], off));
            mB[r] = fmaxf(mB[r], __shfl_xor_sync(0xffffffffu, mB[r], off));
        }
    }
    __syncwarp();

    // exponentiate in place
    for (int t = lane; t < 36; t += 32) sD[t] = __expf(sD[t] - mD);
    for (int t = lane; t < 48; t += 32) {
        #pragma unroll
        for (int r = 0; r < 8; r++) {
            sA[r * 48 + t] = __expf(sA[r * 48 + t] - mA[r]);
            sB[r * 48 + t] = __expf(sB[r * 48 + t] - mB[r]);
        }
    }
    __syncwarp();

    // eC2[s][r] = eA[r][s/3] * eD[s>>2]
    for (int s = lane; s < 144; s += 32) {
        float d = sD[s >> 2];
        int jh = s / 3;
        float4 v0, v1;
        v0.x = sA[0 * 48 + jh] * d;  v0.y = sA[1 * 48 + jh] * d;
        v0.z = sA[2 * 48 + jh] * d;  v0.w = sA[3 * 48 + jh] * d;
        v1.x = sA[4 * 48 + jh] * d;  v1.y = sA[5 * 48 + jh] * d;
        v1.z = sA[6 * 48 + jh] * d;  v1.w = sA[7 * 48 + jh] * d;
        *(float4*)&eC2[s * 8]     = v0;
        *(float4*)&eC2[s * 8 + 4] = v1;
    }
    __syncwarp();

    // register b-values: jw = (lane + 32t) % 48 has period 3 in t
    int w0 = lane;
    int w1 = (lane < 16) ? lane + 32 : lane - 16;
    int w2 = lane + 16;
    float bva[8], bvb[8], bvc[8];
    #pragma unroll
    for (int r = 0; r < 8; r++) {
        bva[r] = sB[r * 48 + w0];
        bvb[r] = sB[r * 48 + w1];
        bvc[r] = sB[r * 48 + w2];
    }

    // sumB16[r][phi] into smB (sQ dead)
    if (lane < 24) {
        int r = lane / 3, phi = lane % 3;
        float s16 = 0.f;
        #pragma unroll
        for (int u = 0; u < 16; u++) s16 += sB[r * 48 + phi * 16 + u];
        smB[r * 3 + phi] = s16;
    }
    __syncwarp();

    // row sums: ssum[r] = sum_s eC2[s][r] * sumB16[r][s%3]; reduce and park in rsum
    {
        float ssum[8] = {0.f, 0.f, 0.f, 0.f, 0.f, 0.f, 0.f, 0.f};
        for (int s = lane; s < 144; s += 32) {
            int phi = s % 3;
            float4 c0 = *(const float4*)&eC2[s * 8];
            float4 c1 = *(const float4*)&eC2[s * 8 + 4];
            ssum[0] = fmaf(c0.x, smB[0 + phi],  ssum[0]);
            ssum[1] = fmaf(c0.y, smB[3 + phi],  ssum[1]);
            ssum[2] = fmaf(c0.z, smB[6 + phi],  ssum[2]);
            ssum[3] = fmaf(c0.w, smB[9 + phi],  ssum[3]);
            ssum[4] = fmaf(c1.x, smB[12 + phi], ssum[4]);
            ssum[5] = fmaf(c1.y, smB[15 + phi], ssum[5]);
            ssum[6] = fmaf(c1.z, smB[18 + phi], ssum[6]);
            ssum[7] = fmaf(c1.w, smB[21 + phi], ssum[7]);
        }
        #pragma unroll
        for (int off = 16; off; off >>= 1) {
            #pragma unroll
            for (int r = 0; r < 8; r++)
                ssum[r] += __shfl_xor_sync(0xffffffffu, ssum[r], off);
        }
        if (lane == 0) {
            #pragma unroll
            for (int r = 0; r < 8; r++) rsum[r] = ssum[r];
        }
    }
    __syncwarp();

    const ulonglong2* vlo = (const ulonglong2*)g_vlo4 + (size_t)(b * HEADS + hd) * HW;
    const ulonglong2* vhi = (const ulonglong2*)g_vhi4 + (size_t)(b * HEADS + hd) * HW;

    unsigned long long acc[8][4];
    #pragma unroll
    for (int r = 0; r < 8; r++)
        #pragma unroll
        for (int k = 0; k < 4; k++) acc[r][k] = 0ull;

    // main loop: j = lane + 32t, t = 0..71; 3-phase unroll; s = (lane>>4) + 2t
    int j = lane;
    int s = lane >> 4;

#define STEP(JOFS, SOFS, BV) { \
        ulonglong2 L = vlo[j + (JOFS)]; \
        ulonglong2 H = vhi[j + (JOFS)]; \
        float4 c0 = *(const float4*)&eC2[(s + (SOFS)) * 8]; \
        float4 c1 = *(const float4*)&eC2[(s + (SOFS)) * 8 + 4]; \
        unsigned long long q0, q1, q2, q3, q4, q5, q6, q7; \
        PACK2(q0, __float_as_uint(c0.x * BV[0])); \
        PACK2(q1, __float_as_uint(c0.y * BV[1])); \
        PACK2(q2, __float_as_uint(c0.z * BV[2])); \
        PACK2(q3, __float_as_uint(c0.w * BV[3])); \
        PACK2(q4, __float_as_uint(c1.x * BV[4])); \
        PACK2(q5, __float_as_uint(c1.y * BV[5])); \
        PACK2(q6, __float_as_uint(c1.z * BV[6])); \
        PACK2(q7, __float_as_uint(c1.w * BV[7])); \
        FMA2(acc[0][0], q0, L.x, acc[0][0]); FMA2(acc[0][1], q0, L.y, acc[0][1]); \
        FMA2(acc[0][2], q0, H.x, acc[0][2]); FMA2(acc[0][3], q0, H.y, acc[0][3]); \
        FMA2(acc[1][0], q1, L.x, acc[1][0]); FMA2(acc[1][1], q1, L.y, acc[1][1]); \
        FMA2(acc[1][2], q1, H.x, acc[1][2]); FMA2(acc[1][3], q1, H.y, acc[1][3]); \
        FMA2(acc[2][0], q2, L.x, acc[2][0]); FMA2(acc[2][1], q2, L.y, acc[2][1]); \
        FMA2(acc[2][2], q2, H.x, acc[2][2]); FMA2(acc[2][3], q2, H.y, acc[2][3]); \
        FMA2(acc[3][0], q3, L.x, acc[3][0]); FMA2(acc[3][1], q3, L.y, acc[3][1]); \
        FMA2(acc[3][2], q3, H.x, acc[3][2]); FMA2(acc[3][3], q3, H.y, acc[3][3]); \
        FMA2(acc[4][0], q4, L.x, acc[4][0]); FMA2(acc[4][1], q4, L.y, acc[4][1]); \
        FMA2(acc[4][2], q4, H.x, acc[4][2]); FMA2(acc[4][3], q4, H.y, acc[4][3]); \
        FMA2(acc[5][0], q5, L.x, acc[5][0]); FMA2(acc[5][1], q5, L.y, acc[5][1]); \
        FMA2(acc[5][2], q5, H.x, acc[5][2]); FMA2(acc[5][3], q5, H.y, acc[5][3]); \
        FMA2(acc[6][0], q6, L.x, acc[6][0]); FMA2(acc[6][1], q6, L.y, acc[6][1]); \
        FMA2(acc[6][2], q6, H.x, acc[6][2]); FMA2(acc[6][3], q6, H.y, acc[6][3]); \
        FMA2(acc[7][0], q7, L.x, acc[7][0]); FMA2(acc[7][1], q7, L.y, acc[7][1]); \
        FMA2(acc[7][2], q7, H.x, acc[7][2]); FMA2(acc[7][3], q7, H.y, acc[7][3]); \
    }

    #pragma unroll 1
    for (int tt = 0; tt < 24; tt++) {
        STEP(0,  0, bva)
        STEP(32, 2, bvb)
        STEP(64, 4, bvc)
        j += 96;
        s += 6;
    }
#undef STEP

    // reduce + write 8 rows
    #pragma unroll
    for (int r = 0; r < 8; r++) {
        float f0, f1, f2, f3, f4, f5, f6, f7;
        unsigned u0, u1;
        UNPK2(u0, u1, acc[r][0]); f0 = __uint_as_float(u0); f1 = __uint_as_float(u1);
        UNPK2(u0, u1, acc[r][1]); f2 = __uint_as_float(u0); f3 = __uint_as_float(u1);
        UNPK2(u0, u1, acc[r][2]); f4 = __uint_as_float(u0); f5 = __uint_as_float(u1);
        UNPK2(u0, u1, acc[r][3]); f6 = __uint_as_float(u0); f7 = __uint_as_float(u1);
        #pragma unroll
        for (int off = 16; off; off >>= 1) {
            f0 += __shfl_xor_sync(0xffffffffu, f0, off);
            f1 += __shfl_xor_sync(0xffffffffu, f1, off);
            f2 += __shfl_xor_sync(0xffffffffu, f2, off);
            f3 += __shfl_xor_sync(0xffffffffu, f3, off);
            f4 += __shfl_xor_sync(0xffffffffu, f4, off);
            f5 += __shfl_xor_sync(0xffffffffu, f5, off);
            f6 += __shfl_xor_sync(0xffffffffu, f6, off);
            f7 += __shfl_xor_sync(0xffffffffu, f7, off);
        }
        float rr = f0;
        if (lane == 1) rr = f1;
        if (lane == 2) rr = f2;
        if (lane == 3) rr = f3;
        if (lane == 4) rr = f4;
        if (lane == 5) rr = f5;
        if (lane == 6) rr = f6;
        if (lane == 7) rr = f7;
        if (lane < 8)
            out[((size_t)(b * 64) + hd * 8 + lane) * HW + i0 + r] = rr / rsum[r];
    }
}

// ---------------- launch ----------------
extern "C" void kernel_launch(void* const* d_in, const int* in_sizes, int n_in,
                              void* d_out, int out_size) {
    const float* f    = (const float*)d_in[0];
    const float* wqkv = (const float*)d_in[1];
    const float* wq   = (const float*)d_in[2];
    const float* bq   = (const float*)d_in[3];
    const float* wk   = (const float*)d_in[4];
    const float* bk   = (const float*)d_in[5];
    const float* ph   = (const float*)d_in[6];
    const float* pw   = (const float*)d_in[7];
    float* out = (float*)d_out;

    qkv_kernel<<<1152, 256>>>(f, wqkv);
    conv_kernel<<<512, 288>>>(wq, bq, wk, bk);
    attn_kernel<<<1152, 128>>>(ph, pw, out);
}